// round 8
// baseline (speedup 1.0000x reference)
#include <cuda_runtime.h>

// Decoder_predict: batched greedy goals-NMS.  B=256, N=4096, T=30, K=6.
// scores = class * centerness, thr^2 = 4.0.
//
// V8: latency-chain attack on top of V7's byte diet (phase 1 reads only
// cls+cent = 8 MB; coords gathered for survivors only).
//  - Phase 1: 32-bit score keys, contiguous idx per thread (8*tid+j) so
//    ballot lowest-lane+slot == exact lowest-index tie-break. Winning lane
//    issues its survivor's float2 coord load IMMEDIATELY (16 warps parallel)
//    -> coord gather latency overlapped with the reduction rounds.
//  - Phase 2: warp 0 NMS over 96 survivors entirely from smem; publishes
//    each round's selection via smem flag + threadfence_block.
//  - Phase 3: warps 1-6 spin on their round's flag and gather that traj row
//    (15 x float4) as soon as it resolves; warp 7 writes probs/goals on the
//    last flag. Single __syncthreads in the whole kernel.

#define NMS_B 256
#define NMS_N 4096
#define NMS_T 30
#define NMS_K 6
#define NMS_THR2 4.0f
#define THREADS 512
#define WARPS 16
#define SURV (WARPS * NMS_K)   // 96

__global__ __launch_bounds__(THREADS, 2)
void nms_goals_kernel(const float* __restrict__ coord,   // [B,1,N,2]
                      const float* __restrict__ cls,     // [B,1,N]
                      const float* __restrict__ traj,    // [B,1,N,T,2]
                      const float* __restrict__ cent,    // [B,1,N]
                      float* __restrict__ out)
{
    const int b    = blockIdx.x;
    const int tid  = threadIdx.x;
    const int wid  = tid >> 5;
    const int lane = tid & 31;

    __shared__ unsigned long long skey[SURV];   // (score_bits<<32)|~idx, 0 = none
    __shared__ float2 scoord[SURV];
    __shared__ float  sel_x[NMS_K], sel_y[NMS_K], sel_s[NMS_K];
    __shared__ int    sel_i[NMS_K];
    __shared__ volatile int flags[NMS_K];

    if (tid < NMS_K) flags[tid] = 0;

    // ---- Phase 1: scores only, 8 contiguous candidates per thread. ----
    {
        const float4* s4 = (const float4*)(cls  + (size_t)b * NMS_N);
        const float4* e4 = (const float4*)(cent + (size_t)b * NMS_N);
        const float2* cptr = (const float2*)(coord + (size_t)b * NMS_N * 2);

        const float4 sa = s4[2 * tid];
        const float4 sb = s4[2 * tid + 1];
        const float4 ea = e4[2 * tid];
        const float4 eb = e4[2 * tid + 1];

        unsigned sc[8];
        sc[0] = __float_as_uint(sa.x * ea.x);
        sc[1] = __float_as_uint(sa.y * ea.y);
        sc[2] = __float_as_uint(sa.z * ea.z);
        sc[3] = __float_as_uint(sa.w * ea.w);
        sc[4] = __float_as_uint(sb.x * eb.x);
        sc[5] = __float_as_uint(sb.y * eb.y);
        sc[6] = __float_as_uint(sb.z * eb.z);
        sc[7] = __float_as_uint(sb.w * eb.w);

        unsigned tmax = sc[0];
#pragma unroll
        for (int j = 1; j < 8; j++) tmax = max(tmax, sc[j]);

        float2 cvr[NMS_K];
        bool   wr[NMS_K];
#pragma unroll
        for (int r = 0; r < NMS_K; r++) wr[r] = false;

#pragma unroll
        for (int r = 0; r < NMS_K; r++) {
            unsigned m = tmax;
#pragma unroll
            for (int off = 16; off > 0; off >>= 1)
                m = max(m, __shfl_xor_sync(0xFFFFFFFFu, m, off));

            if (m == 0u) {
                if (lane == 0) skey[wid * NMS_K + r] = 0ULL;   // empty slot
            } else {
                const bool mine = (tmax == m);
                const unsigned bal = __ballot_sync(0xFFFFFFFFu, mine);
                const int wl = __ffs(bal) - 1;   // lowest lane = lowest idx
                if (lane == wl) {
                    int jm = 7;
#pragma unroll
                    for (int j = 7; j >= 0; j--)
                        if (sc[j] == m) jm = j;   // lowest slot = lowest idx
                    const unsigned idx = 8u * (unsigned)tid + (unsigned)jm;
                    skey[wid * NMS_K + r] =
                        ((unsigned long long)m << 32) | (unsigned)(~idx);
                    cvr[r] = cptr[idx];           // overlapped coord gather
                    wr[r]  = true;
#pragma unroll
                    for (int j = 0; j < 8; j++) if (sc[j] == m) sc[j] = 0u;
                    tmax = sc[0];
#pragma unroll
                    for (int j = 1; j < 8; j++) tmax = max(tmax, sc[j]);
                }
            }
        }
#pragma unroll
        for (int r = 0; r < NMS_K; r++)
            if (wr[r]) scoord[wid * NMS_K + r] = cvr[r];
    }
    __syncthreads();    // the only block barrier

    // ---- Phase 2: warp 0 greedy NMS over 96 survivors (3/lane, smem). ----
    if (wid == 0) {
        unsigned long long vp[3];
        float vx[3], vy[3];
#pragma unroll
        for (int h = 0; h < 3; h++) {
            vp[h] = skey[lane + 32 * h];
            const float2 c = scoord[lane + 32 * h];
            vx[h] = c.x;  vy[h] = c.y;
        }
#pragma unroll
        for (int r = 0; r < NMS_K; r++) {
            unsigned long long m = max(max(vp[0], vp[1]), vp[2]);
#pragma unroll
            for (int off = 16; off > 0; off >>= 1)
                m = max(m, __shfl_xor_sync(0xFFFFFFFFu, m, off));

            if (m == 0ULL) {
                if (lane == 0) {
                    sel_i[r] = -1; sel_s[r] = 0.0f;
                    sel_x[r] = 0.0f; sel_y[r] = 0.0f;
                    __threadfence_block();
                    flags[r] = 1;
                }
            } else {
                int hm = -1;
#pragma unroll
                for (int h = 0; h < 3; h++) if (vp[h] == m) hm = h;
                const unsigned bal = __ballot_sync(0xFFFFFFFFu, hm >= 0);
                const int wl = __ffs(bal) - 1;
                float fx = 0.f, fy = 0.f;
#pragma unroll
                for (int h = 0; h < 3; h++) if (h == hm) { fx = vx[h]; fy = vy[h]; }
                const float px = __shfl_sync(0xFFFFFFFFu, fx, wl);
                const float py = __shfl_sync(0xFFFFFFFFu, fy, wl);
                if (lane == wl) {
                    sel_x[r] = px;  sel_y[r] = py;
                    sel_s[r] = __uint_as_float((unsigned)(m >> 32));
                    sel_i[r] = (int)(~(unsigned)(m & 0xFFFFFFFFu));
                    __threadfence_block();
                    flags[r] = 1;     // release this round's selection
                }
                // Suppress survivors within thr (incl. the winner itself).
#pragma unroll
                for (int h = 0; h < 3; h++) {
                    const float dx = vx[h] - px;
                    const float dy = vy[h] - py;
                    if (dx * dx + dy * dy < NMS_THR2) vp[h] = 0ULL;
                }
            }
            __syncwarp();   // order this round's stores before next round
        }
    }
    // ---- Phase 3: consumers start as soon as their round resolves. ----
    else if (wid <= NMS_K) {            // warps 1..6 -> traj row (wid-1)
        const int r = wid - 1;
        while (flags[r] == 0) { }
        __threadfence_block();
        const int s0  = sel_i[0];
        const int sr  = sel_i[r];
        const int src = (sr >= 0) ? sr : s0;
        if (lane < 15) {
            ((float4*)out)[((size_t)b * NMS_K + r) * 15 + lane] =
                ((const float4*)traj)[((size_t)b * NMS_N + src) * 15 + lane];
        }
    }
    else if (wid == 7) {                // probs + goals after last round
        while (flags[NMS_K - 1] == 0) { }
        __threadfence_block();
        float* out_prob = out + (size_t)NMS_B * NMS_K * NMS_T * 2;
        float* out_goal = out_prob + (size_t)NMS_B * NMS_K;
        if (lane < NMS_K) {
            const int  k     = lane;
            const bool valid = (sel_i[k] >= 0);
            out_prob[(size_t)b * NMS_K + k]           = valid ? sel_s[k] : sel_s[0];
            out_goal[((size_t)b * NMS_K + k) * 2 + 0] = valid ? sel_x[k] : 0.0f;
            out_goal[((size_t)b * NMS_K + k) * 2 + 1] = valid ? sel_y[k] : 0.0f;
        }
    }
    // warps 8..15: done after phase 1.
}

extern "C" void kernel_launch(void* const* d_in, const int* in_sizes, int n_in,
                              void* d_out, int out_size) {
    const float* coord = (const float*)d_in[0];  // outputs_coord     [B,1,N,2]
    const float* cls   = (const float*)d_in[1];  // outputs_class     [B,1,N]
    const float* traj  = (const float*)d_in[2];  // outputs_traj      [B,1,N,T,2]
    const float* cent  = (const float*)d_in[3];  // outputs_centerness[B,1,N]
    float* out = (float*)d_out;

    nms_goals_kernel<<<NMS_B, THREADS>>>(coord, cls, traj, cent, out);
}